// round 1
// baseline (speedup 1.0000x reference)
#include <cuda_runtime.h>
#include <math.h>

// ---------------- problem constants ----------------
#define NB   8      // batch
#define NN   200    // sensors / nodes
#define NS   96     // seq
#define ND   128    // d_model
#define NBS  768    // NB*NS
#define NROWS 153600 // NB*NN*NS
#define OFFH 19660800 // NN*NBS*ND  (per-map tensor size)

// ---------------- scratch (static device globals; no allocs allowed) ----------
__device__ float g_W2[128 * 256];        // summed conv weights, [d][map*128+g]
__device__ float g_bsum[256];            // summed conv bias per channel
__device__ float g_map1raw[200 * 200];   // mean attention map
__device__ float g_Msym[2 * 200 * 200];  // thresholded symmetric maps
__device__ float g_dinv[2 * 200];        // rsqrt(deg)
__device__ float g_An[2 * 200 * 200];    // normalized adjacency
__device__ float g_xw[2 * OFFH];         // X @ Wsum  in [map][n][bs][d]
__device__ float g_h[2 * OFFH];          // An @ xw   in [map][m][bs][d]
__device__ float g_stats[512];           // [sum(256), sumsq(256)]
__device__ float g_scale[256];
__device__ float g_bias[256];

// ---------------- small prep kernels ----------------

// mean of attn_s[0] over (batch, heads): 64 matrices of 200x200
__global__ void k_attn_mean(const float* __restrict__ attn) {
    int e = blockIdx.x * 256 + threadIdx.x;
    if (e >= 40000) return;
    float s = 0.f;
#pragma unroll 8
    for (int t = 0; t < 64; t++) s += attn[t * 40000 + e];
    g_map1raw[e] = s * (1.f / 64.f);
}

// W2[d][c] = W_conv[i,0,d,g] + W_conv[i,1,d,g]  (c = i*128+g); also bsum, zero stats
__global__ void k_prep(const float* __restrict__ Wc, const float* __restrict__ bc) {
    int id = blockIdx.x * 256 + threadIdx.x;
    if (id < 32768) {
        int d = id >> 8;
        int c = id & 255;
        int i = c >> 7;
        int g = c & 127;
        g_W2[id] = Wc[((i * 2 + 0) * 128 + d) * 128 + g] +
                   Wc[((i * 2 + 1) * 128 + d) * 128 + g];
    }
    if (id < 512) g_stats[id] = 0.f;
    if (id < 256) {
        int i = id >> 7, g = id & 127;
        g_bsum[id] = bc[(i * 2 + 0) * 128 + g] + bc[(i * 2 + 1) * 128 + g];
    }
}

// symmetrize + abs-threshold one row; compute rsqrt(rowsum + selfloop)
__global__ void k_procmap(const float* __restrict__ supports) {
    int m = blockIdx.x;
    int mi = blockIdx.y;
    int t = threadIdx.x;
    const float* src = (mi == 0) ? supports : g_map1raw;
    float v = 0.f;
    if (t < 200) {
        float a = (m >= t) ? src[m * 200 + t] : src[t * 200 + m];
        float aa = fabsf(a);
        v = (aa > 0.01f) ? aa : 0.f;
        g_Msym[mi * 40000 + m * 200 + t] = v;
    }
    // block reduce (256 threads = 8 warps)
    __shared__ float red[8];
    float s = v;
#pragma unroll
    for (int o = 16; o; o >>= 1) s += __shfl_xor_sync(0xffffffffu, s, o);
    if ((t & 31) == 0) red[t >> 5] = s;
    __syncthreads();
    if (t == 0) {
        float tot = 1.0f;  // self loop
#pragma unroll
        for (int w = 0; w < 8; w++) tot += red[w];
        g_dinv[mi * 200 + m] = (tot > 0.f) ? rsqrtf(tot) : 0.f;
    }
}

// An = D^-1/2 (M + I) D^-1/2
__global__ void k_norm() {
    int id = blockIdx.x * 256 + threadIdx.x;
    if (id >= 80000) return;
    int mi = id / 40000;
    int rem = id - mi * 40000;
    int m = rem / 200;
    int n = rem - m * 200;
    float a = g_Msym[id] + ((m == n) ? 1.f : 0.f);
    g_An[id] = g_dinv[mi * 200 + m] * a * g_dinv[mi * 200 + n];
}

// BN params: scale/bias per channel from accumulated sum/sumsq
__global__ void k_bnparams(const float* __restrict__ gamma, const float* __restrict__ beta) {
    int c = threadIdx.x;  // 256
    const float inv = 1.f / 153600.f;
    float mu = g_stats[c] * inv;
    float var = g_stats[256 + c] * inv - mu * mu;
    float sc = gamma[c] * rsqrtf(var + 1e-5f);
    g_scale[c] = sc;
    g_bias[c] = beta[c] - mu * sc;
}

// ---------------- GEMM 1: xw = X @ W2  (153600x128 @ 128x256) ----------------
// store into g_xw in [map][n][bs][d] layout
__global__ __launch_bounds__(256) void k_gemm_xw(const float* __restrict__ X) {
    __shared__ float As[8][128];
    __shared__ float Bs[8][128];
    int tid = threadIdx.x;
    int tx = tid & 15, ty = tid >> 4;
    int imap = blockIdx.x;            // column tile == map (BN=128)
    int cn0 = imap << 7;
    int r0 = blockIdx.y << 7;

    float acc[8][8];
#pragma unroll
    for (int i = 0; i < 8; i++)
#pragma unroll
        for (int j = 0; j < 8; j++) acc[i][j] = 0.f;

    int aRow = tid >> 1, aCol = (tid & 1) << 2;
    int bRow = tid >> 5, bCol = (tid & 31) << 2;
    const float* Aptr = X + (size_t)(r0 + aRow) * 128 + aCol;
    const float* Bptr = g_W2 + bRow * 256 + cn0 + bCol;

    for (int k0 = 0; k0 < 128; k0 += 8) {
        float4 av = *(const float4*)(Aptr + k0);
        As[aCol + 0][aRow] = av.x;
        As[aCol + 1][aRow] = av.y;
        As[aCol + 2][aRow] = av.z;
        As[aCol + 3][aRow] = av.w;
        float4 bv = *(const float4*)(Bptr + k0 * 256);
        *(float4*)&Bs[bRow][bCol] = bv;
        __syncthreads();
#pragma unroll
        for (int k = 0; k < 8; k++) {
            float4 a0 = *(const float4*)&As[k][ty << 3];
            float4 a1 = *(const float4*)&As[k][(ty << 3) + 4];
            float4 b0 = *(const float4*)&Bs[k][tx << 3];
            float4 b1 = *(const float4*)&Bs[k][(tx << 3) + 4];
            float ar[8] = {a0.x, a0.y, a0.z, a0.w, a1.x, a1.y, a1.z, a1.w};
            float br[8] = {b0.x, b0.y, b0.z, b0.w, b1.x, b1.y, b1.z, b1.w};
#pragma unroll
            for (int i = 0; i < 8; i++)
#pragma unroll
                for (int j = 0; j < 8; j++) acc[i][j] = fmaf(ar[i], br[j], acc[i][j]);
        }
        __syncthreads();
    }

#pragma unroll
    for (int ii = 0; ii < 8; ii++) {
        int r = r0 + (ty << 3) + ii;         // r = (b*200+n)*96+s
        int b = r / 19200;
        int rem = r - b * 19200;
        int n = rem / 96;
        int s = rem - n * 96;
        int bs = b * 96 + s;
        float* dst = g_xw + ((size_t)(imap * 200 + n) * 768 + bs) * 128 + (tx << 3);
        *(float4*)dst = make_float4(acc[ii][0], acc[ii][1], acc[ii][2], acc[ii][3]);
        *(float4*)(dst + 4) = make_float4(acc[ii][4], acc[ii][5], acc[ii][6], acc[ii][7]);
    }
}

// ---------------- GEMM 2: h = An @ xw  ([200,200] @ [200, 98304] per map) -----
// + fused bias + BN-statistics epilogue (atomic per-channel sum/sumsq)
__global__ __launch_bounds__(256) void k_gemm_an() {
    __shared__ float As[8][128];
    __shared__ float Bs[8][128];
    __shared__ float redS[16][128];
    __shared__ float redQ[16][128];
    int tid = threadIdx.x;
    int tx = tid & 15, ty = tid >> 4;
    int bx = blockIdx.x;          // bs index (column tile of width 128 == D)
    int m0 = blockIdx.y << 7;     // 0 or 128 (M=200, padded)
    int mi = blockIdx.z;

    float acc[8][8];
#pragma unroll
    for (int i = 0; i < 8; i++)
#pragma unroll
        for (int j = 0; j < 8; j++) acc[i][j] = 0.f;

    int aRow = tid >> 1, aCol = (tid & 1) << 2;
    int bRow = tid >> 5, bCol = (tid & 31) << 2;
    const float* Abase = g_An + mi * 40000;
    const float* Bbase = g_xw + (size_t)mi * OFFH;
    int am = m0 + aRow;
    bool aValid = (am < 200);

    for (int k0 = 0; k0 < 200; k0 += 8) {
        float4 av = aValid ? *(const float4*)(Abase + am * 200 + k0 + aCol)
                           : make_float4(0.f, 0.f, 0.f, 0.f);
        As[aCol + 0][aRow] = av.x;
        As[aCol + 1][aRow] = av.y;
        As[aCol + 2][aRow] = av.z;
        As[aCol + 3][aRow] = av.w;
        float4 bv = *(const float4*)(Bbase + (size_t)(k0 + bRow) * 98304 + bx * 128 + bCol);
        *(float4*)&Bs[bRow][bCol] = bv;
        __syncthreads();
#pragma unroll
        for (int k = 0; k < 8; k++) {
            float4 a0 = *(const float4*)&As[k][ty << 3];
            float4 a1 = *(const float4*)&As[k][(ty << 3) + 4];
            float4 b0 = *(const float4*)&Bs[k][tx << 3];
            float4 b1 = *(const float4*)&Bs[k][(tx << 3) + 4];
            float ar[8] = {a0.x, a0.y, a0.z, a0.w, a1.x, a1.y, a1.z, a1.w};
            float br[8] = {b0.x, b0.y, b0.z, b0.w, b1.x, b1.y, b1.z, b1.w};
#pragma unroll
            for (int i = 0; i < 8; i++)
#pragma unroll
                for (int j = 0; j < 8; j++) acc[i][j] = fmaf(ar[i], br[j], acc[i][j]);
        }
        __syncthreads();
    }

    // epilogue: add conv bias, store h, accumulate column sum/sumsq (valid rows only)
    float bb[8];
#pragma unroll
    for (int j = 0; j < 8; j++) bb[j] = g_bsum[mi * 128 + (tx << 3) + j];
    float cs[8], cq[8];
#pragma unroll
    for (int j = 0; j < 8; j++) { cs[j] = 0.f; cq[j] = 0.f; }

#pragma unroll
    for (int ii = 0; ii < 8; ii++) {
        int m = m0 + (ty << 3) + ii;
        if (m < 200) {
            float h[8];
#pragma unroll
            for (int j = 0; j < 8; j++) h[j] = acc[ii][j] + bb[j];
            float* dst = g_h + (size_t)mi * OFFH + ((size_t)m * 768 + bx) * 128 + (tx << 3);
            *(float4*)dst = make_float4(h[0], h[1], h[2], h[3]);
            *(float4*)(dst + 4) = make_float4(h[4], h[5], h[6], h[7]);
#pragma unroll
            for (int j = 0; j < 8; j++) {
                cs[j] += h[j];
                cq[j] += h[j] * h[j];
            }
        }
    }
#pragma unroll
    for (int j = 0; j < 8; j++) {
        redS[ty][(tx << 3) + j] = cs[j];
        redQ[ty][(tx << 3) + j] = cq[j];
    }
    __syncthreads();
    if (tid < 128) {
        float s = 0.f, q = 0.f;
#pragma unroll
        for (int t = 0; t < 16; t++) {
            s += redS[t][tid];
            q += redQ[t][tid];
        }
        atomicAdd(&g_stats[mi * 128 + tid], s);
        atomicAdd(&g_stats[256 + mi * 128 + tid], q);
    }
}

// ---------------- GEMM 3: out = relu( relu(BN(h)) @ W_out + b_out ) ----------
// A-operand (153600 x 256) materialized on the fly from the two h tensors with
// fused affine+relu; output store fuses the [bs,n,d]->[b,n,s,d] transpose.
__global__ __launch_bounds__(256) void k_gemm_out(const float* __restrict__ Wout,
                                                  const float* __restrict__ bout,
                                                  float* __restrict__ out) {
    __shared__ float As[8][128];
    __shared__ float Bs[8][128];
    __shared__ float sSc[256], sBi[256], sBo[128];
    int tid = threadIdx.x;
    sSc[tid] = g_scale[tid];
    sBi[tid] = g_bias[tid];
    if (tid < 128) sBo[tid] = bout[tid];
    __syncthreads();

    int tx = tid & 15, ty = tid >> 4;
    int r0 = blockIdx.x << 7;   // row = n*768 + bs

    float acc[8][8];
#pragma unroll
    for (int i = 0; i < 8; i++)
#pragma unroll
        for (int j = 0; j < 8; j++) acc[i][j] = 0.f;

    int aRow = tid >> 1, aCol = (tid & 1) << 2;
    int bRow = tid >> 5, bCol = (tid & 31) << 2;
    int r = r0 + aRow;

    for (int k0 = 0; k0 < 256; k0 += 8) {
        int k = k0 + aCol;
        int mp = k >> 7;
        int kk = k & 127;
        float4 v = *(const float4*)(g_h + (size_t)mp * OFFH + (size_t)r * 128 + kk);
        v.x = fmaxf(fmaf(v.x, sSc[k + 0], sBi[k + 0]), 0.f);
        v.y = fmaxf(fmaf(v.y, sSc[k + 1], sBi[k + 1]), 0.f);
        v.z = fmaxf(fmaf(v.z, sSc[k + 2], sBi[k + 2]), 0.f);
        v.w = fmaxf(fmaf(v.w, sSc[k + 3], sBi[k + 3]), 0.f);
        As[aCol + 0][aRow] = v.x;
        As[aCol + 1][aRow] = v.y;
        As[aCol + 2][aRow] = v.z;
        As[aCol + 3][aRow] = v.w;
        float4 bv = *(const float4*)(Wout + (k0 + bRow) * 128 + bCol);
        *(float4*)&Bs[bRow][bCol] = bv;
        __syncthreads();
#pragma unroll
        for (int k2 = 0; k2 < 8; k2++) {
            float4 a0 = *(const float4*)&As[k2][ty << 3];
            float4 a1 = *(const float4*)&As[k2][(ty << 3) + 4];
            float4 b0 = *(const float4*)&Bs[k2][tx << 3];
            float4 b1 = *(const float4*)&Bs[k2][(tx << 3) + 4];
            float ar[8] = {a0.x, a0.y, a0.z, a0.w, a1.x, a1.y, a1.z, a1.w};
            float br[8] = {b0.x, b0.y, b0.z, b0.w, b1.x, b1.y, b1.z, b1.w};
#pragma unroll
            for (int i = 0; i < 8; i++)
#pragma unroll
                for (int j = 0; j < 8; j++) acc[i][j] = fmaf(ar[i], br[j], acc[i][j]);
        }
        __syncthreads();
    }

#pragma unroll
    for (int ii = 0; ii < 8; ii++) {
        int rr = r0 + (ty << 3) + ii;
        int n = rr / 768;
        int bs = rr - n * 768;
        int b = bs / 96;
        int s = bs - b * 96;
        float* dst = out + (((size_t)b * 200 + n) * 96 + s) * 128 + (tx << 3);
        float4 o0, o1;
        o0.x = fmaxf(acc[ii][0] + sBo[(tx << 3) + 0], 0.f);
        o0.y = fmaxf(acc[ii][1] + sBo[(tx << 3) + 1], 0.f);
        o0.z = fmaxf(acc[ii][2] + sBo[(tx << 3) + 2], 0.f);
        o0.w = fmaxf(acc[ii][3] + sBo[(tx << 3) + 3], 0.f);
        o1.x = fmaxf(acc[ii][4] + sBo[(tx << 3) + 4], 0.f);
        o1.y = fmaxf(acc[ii][5] + sBo[(tx << 3) + 5], 0.f);
        o1.z = fmaxf(acc[ii][6] + sBo[(tx << 3) + 6], 0.f);
        o1.w = fmaxf(acc[ii][7] + sBo[(tx << 3) + 7], 0.f);
        *(float4*)dst = o0;
        *(float4*)(dst + 4) = o1;
    }
}

// ---------------- launch ----------------
extern "C" void kernel_launch(void* const* d_in, const int* in_sizes, int n_in,
                              void* d_out, int out_size) {
    const float* x        = (const float*)d_in[0];
    const float* attn     = (const float*)d_in[1];
    const float* supports = (const float*)d_in[2];
    const float* Wc       = (const float*)d_in[3];
    const float* bc       = (const float*)d_in[4];
    const float* gamma    = (const float*)d_in[5];
    const float* beta     = (const float*)d_in[6];
    const float* Wout     = (const float*)d_in[7];
    const float* bout     = (const float*)d_in[8];
    float* out = (float*)d_out;

    k_attn_mean<<<157, 256>>>(attn);
    k_prep<<<128, 256>>>(Wc, bc);
    k_procmap<<<dim3(200, 2), 256>>>(supports);
    k_norm<<<313, 256>>>();
    k_gemm_xw<<<dim3(2, 1200), 256>>>(x);
    k_gemm_an<<<dim3(768, 2, 2), 256>>>();
    k_bnparams<<<1, 256>>>(gamma, beta);
    k_gemm_out<<<1200, 256>>>(Wout, bout, out);
}

// round 2
// speedup vs baseline: 2.0942x; 2.0942x over previous
#include <cuda_runtime.h>
#include <math.h>
#include <stdint.h>

// ---------------- problem constants ----------------
#define OFFH2 19660800ULL   // 200*768*128 per-map h tensor

// ---------------- scratch (static device globals) ----------------
__device__ float g_W2[128 * 256];          // summed conv weights [k][map*128+g]
__device__ float g_bsum[256];
__device__ float g_map1raw[200 * 200];
__device__ float g_Msym[2 * 200 * 200];
__device__ float g_dinv[2 * 200];
__device__ float g_An[2 * 256 * 208];      // padded normalized adjacency
__device__ float g_xw[2ULL * 208 * 98304]; // [map][n(208)][bs][d]
__device__ float g_h[2ULL * 19660800ULL];  // [map][m*768+bs][d]
__device__ float g_stats[512];
__device__ float g_scale[256];
__device__ float g_bias[256];

// ---------------- tf32 helpers ----------------
__device__ __forceinline__ uint32_t f2tf(float x) {
    uint32_t r;
    asm("cvt.rna.tf32.f32 %0, %1;" : "=r"(r) : "f"(x));
    return r;
}

__device__ __forceinline__ void mma_tf32(float* d, const uint32_t* a, const uint32_t* b) {
    asm volatile(
        "mma.sync.aligned.m16n8k8.row.col.f32.tf32.tf32.f32 "
        "{%0,%1,%2,%3}, {%4,%5,%6,%7}, {%8,%9}, {%0,%1,%2,%3};"
        : "+f"(d[0]), "+f"(d[1]), "+f"(d[2]), "+f"(d[3])
        : "r"(a[0]), "r"(a[1]), "r"(a[2]), "r"(a[3]), "r"(b[0]), "r"(b[1]));
}

// one BK=16 tile of 128x128 per block; warp tile 32x64 (2 mtiles x 8 ntiles)
__device__ __forceinline__ void compute_tile(const uint32_t (*As)[20],
                                             const uint32_t (*Bs)[136],
                                             float acc[2][8][4],
                                             int m_off, int n_off, int q, int c) {
#pragma unroll
    for (int s = 0; s < 2; s++) {
        const int ks = s << 3;
        uint32_t a[2][4];
#pragma unroll
        for (int i = 0; i < 2; i++) {
            const int mr = m_off + (i << 4) + q;
            a[i][0] = As[mr][ks + c];
            a[i][1] = As[mr + 8][ks + c];
            a[i][2] = As[mr][ks + c + 4];
            a[i][3] = As[mr + 8][ks + c + 4];
        }
        uint32_t b[8][2];
#pragma unroll
        for (int j = 0; j < 8; j++) {
            const int nn = n_off + (j << 3) + q;
            b[j][0] = Bs[ks + c][nn];
            b[j][1] = Bs[ks + c + 4][nn];
        }
#pragma unroll
        for (int i = 0; i < 2; i++)
#pragma unroll
            for (int j = 0; j < 8; j++) mma_tf32(acc[i][j], a[i], b[j]);
    }
}

// ---------------- small prep kernels ----------------
__global__ void k_attn_mean(const float* __restrict__ attn) {
    int e = blockIdx.x * 256 + threadIdx.x;
    if (e >= 40000) return;
    float s = 0.f;
#pragma unroll 8
    for (int t = 0; t < 64; t++) s += attn[t * 40000 + e];
    g_map1raw[e] = s * (1.f / 64.f);
}

__global__ void k_prep(const float* __restrict__ Wc, const float* __restrict__ bc) {
    int id = blockIdx.x * 256 + threadIdx.x;
    if (id < 32768) {
        int d = id >> 8;
        int cc = id & 255;
        int i = cc >> 7;
        int g = cc & 127;
        g_W2[id] = Wc[((i * 2 + 0) * 128 + d) * 128 + g] +
                   Wc[((i * 2 + 1) * 128 + d) * 128 + g];
    }
    if (id < 512) g_stats[id] = 0.f;
    if (id < 256) {
        int i = id >> 7, g = id & 127;
        g_bsum[id] = bc[(i * 2 + 0) * 128 + g] + bc[(i * 2 + 1) * 128 + g];
    }
}

__global__ void k_procmap(const float* __restrict__ supports) {
    int m = blockIdx.x;
    int mi = blockIdx.y;
    int t = threadIdx.x;
    const float* src = (mi == 0) ? supports : g_map1raw;
    float v = 0.f;
    if (t < 200) {
        float a = (m >= t) ? src[m * 200 + t] : src[t * 200 + m];
        float aa = fabsf(a);
        v = (aa > 0.01f) ? aa : 0.f;
        g_Msym[mi * 40000 + m * 200 + t] = v;
    }
    __shared__ float red[8];
    float s = v;
#pragma unroll
    for (int o = 16; o; o >>= 1) s += __shfl_xor_sync(0xffffffffu, s, o);
    if ((t & 31) == 0) red[t >> 5] = s;
    __syncthreads();
    if (t == 0) {
        float tot = 1.0f;
#pragma unroll
        for (int w = 0; w < 8; w++) tot += red[w];
        g_dinv[mi * 200 + m] = (tot > 0.f) ? rsqrtf(tot) : 0.f;
    }
}

// An padded to [2][256][208], zeros outside [200,200)
__global__ void k_norm_pad() {
    int id = blockIdx.x * 256 + threadIdx.x;
    if (id >= 2 * 256 * 208) return;
    int mi = id / (256 * 208);
    int rem = id - mi * 256 * 208;
    int m = rem / 208;
    int k = rem - m * 208;
    float val = 0.f;
    if (m < 200 && k < 200) {
        float a = g_Msym[mi * 40000 + m * 200 + k] + ((m == k) ? 1.f : 0.f);
        val = g_dinv[mi * 200 + m] * a * g_dinv[mi * 200 + k];
    }
    g_An[id] = val;
}

// zero g_xw pad rows n in [200,208)
__global__ void k_zero_xwpad() {
    int idx = blockIdx.x * 256 + threadIdx.x;   // float4 index, total 393216
    int mi = idx / 196608;
    int r = idx - mi * 196608;
    int n = 200 + r / 24576;
    int cc = (r - (n - 200) * 24576) * 4;
    float4 z = make_float4(0.f, 0.f, 0.f, 0.f);
    *(float4*)(g_xw + ((size_t)(mi * 208 + n)) * 98304 + cc) = z;
}

__global__ void k_bnparams(const float* __restrict__ gamma, const float* __restrict__ beta) {
    int c = threadIdx.x;
    const float inv = 1.f / 153600.f;
    float mu = g_stats[c] * inv;
    float var = g_stats[256 + c] * inv - mu * mu;
    float sc = gamma[c] * rsqrtf(var + 1e-5f);
    g_scale[c] = sc;
    g_bias[c] = beta[c] - mu * sc;
}

// ---------------- GEMM 1: xw = X @ W2  (153600x128 @ 128x256) ----------------
__global__ __launch_bounds__(256) void k_gemm_xw(const float* __restrict__ X) {
    __shared__ uint32_t As[2][128][20];
    __shared__ uint32_t Bs[2][16][136];
    const int tid = threadIdx.x;
    const int lane = tid & 31;
    const int q = lane >> 2, c = lane & 3;
    const int m_off = ((tid >> 5) & 3) << 5;
    const int n_off = (tid >> 7) << 6;
    const int mi = blockIdx.x;
    const int r0 = blockIdx.y << 7;

    const int arow = tid & 127, acol = (tid >> 7) << 3;
    const int brow = tid >> 4, bcol = (tid & 15) << 3;

    const float* Ap = X + (size_t)(r0 + arow) * 128 + acol;
    const float* Bp = g_W2 + (size_t)brow * 256 + (mi << 7) + bcol;

    float acc[2][8][4];
#pragma unroll
    for (int i = 0; i < 2; i++)
#pragma unroll
        for (int j = 0; j < 8; j++)
#pragma unroll
            for (int p = 0; p < 4; p++) acc[i][j][p] = 0.f;

    float4 fa0, fa1, fb0, fb1;
#define FETCH1()                                              \
    {                                                         \
        fa0 = *(const float4*)Ap; fa1 = *(const float4*)(Ap + 4); \
        fb0 = *(const float4*)Bp; fb1 = *(const float4*)(Bp + 4); \
        Ap += 16; Bp += 16 * 256;                             \
    }
#define STORE1(b)                                                                 \
    {                                                                             \
        uint4* ap = (uint4*)&As[b][arow][acol];                                   \
        ap[0] = make_uint4(f2tf(fa0.x), f2tf(fa0.y), f2tf(fa0.z), f2tf(fa0.w));   \
        ap[1] = make_uint4(f2tf(fa1.x), f2tf(fa1.y), f2tf(fa1.z), f2tf(fa1.w));   \
        uint4* bp = (uint4*)&Bs[b][brow][bcol];                                   \
        bp[0] = make_uint4(f2tf(fb0.x), f2tf(fb0.y), f2tf(fb0.z), f2tf(fb0.w));   \
        bp[1] = make_uint4(f2tf(fb1.x), f2tf(fb1.y), f2tf(fb1.z), f2tf(fb1.w));   \
    }

    FETCH1();
    STORE1(0);
    __syncthreads();
    int buf = 0;
    const int T = 8;
    for (int t = 0; t < T; t++) {
        bool more = (t + 1 < T);
        if (more) FETCH1();
        compute_tile(As[buf], Bs[buf], acc, m_off, n_off, q, c);
        if (more) STORE1(buf ^ 1);
        __syncthreads();
        buf ^= 1;
    }
#undef FETCH1
#undef STORE1

#pragma unroll
    for (int i = 0; i < 2; i++) {
        int r1 = r0 + m_off + (i << 4) + q;
#pragma unroll
        for (int rh = 0; rh < 2; rh++) {
            int r = r1 + (rh << 3);
            int b = r / 19200;
            int rem = r - b * 19200;
            int n = rem / 96;
            int s = rem - n * 96;
            size_t base = ((size_t)(mi * 208 + n) * 768 + (b * 96 + s)) * 128;
#pragma unroll
            for (int j = 0; j < 8; j++) {
                int cc = n_off + (j << 3) + (c << 1);
                *(float2*)(g_xw + base + cc) =
                    make_float2(acc[i][j][rh * 2], acc[i][j][rh * 2 + 1]);
            }
        }
    }
}

// ---------------- GEMM 2: h = An @ xw  (256x208 @ 208x98304, per map) --------
__global__ __launch_bounds__(256) void k_gemm_an() {
    __shared__ uint32_t As[2][128][20];
    __shared__ uint32_t Bs[2][16][136];
    __shared__ float sS[128], sQ[128];
    const int tid = threadIdx.x;
    const int lane = tid & 31;
    const int q = lane >> 2, c = lane & 3;
    const int m_off = ((tid >> 5) & 3) << 5;
    const int n_off = (tid >> 7) << 6;
    const int bx = blockIdx.x;        // bs
    const int m0 = blockIdx.y << 7;   // 0 / 128
    const int mi = blockIdx.z;

    if (tid < 128) { sS[tid] = 0.f; sQ[tid] = 0.f; }

    const int arow = tid & 127, acol = (tid >> 7) << 3;
    const int brow = tid >> 4, bcol = (tid & 15) << 3;

    const float* Ap = g_An + (size_t)mi * (256 * 208) + (size_t)(m0 + arow) * 208 + acol;
    const float* Bp = g_xw + (size_t)mi * (208ULL * 98304) + (size_t)brow * 98304 +
                      (size_t)bx * 128 + bcol;

    float acc[2][8][4];
#pragma unroll
    for (int i = 0; i < 2; i++)
#pragma unroll
        for (int j = 0; j < 8; j++)
#pragma unroll
            for (int p = 0; p < 4; p++) acc[i][j][p] = 0.f;

    float4 fa0, fa1, fb0, fb1;
#define FETCH2()                                              \
    {                                                         \
        fa0 = *(const float4*)Ap; fa1 = *(const float4*)(Ap + 4); \
        fb0 = *(const float4*)Bp; fb1 = *(const float4*)(Bp + 4); \
        Ap += 16; Bp += (size_t)16 * 98304;                   \
    }
#define STORE2(b)                                                                 \
    {                                                                             \
        uint4* ap = (uint4*)&As[b][arow][acol];                                   \
        ap[0] = make_uint4(f2tf(fa0.x), f2tf(fa0.y), f2tf(fa0.z), f2tf(fa0.w));   \
        ap[1] = make_uint4(f2tf(fa1.x), f2tf(fa1.y), f2tf(fa1.z), f2tf(fa1.w));   \
        uint4* bp = (uint4*)&Bs[b][brow][bcol];                                   \
        bp[0] = make_uint4(f2tf(fb0.x), f2tf(fb0.y), f2tf(fb0.z), f2tf(fb0.w));   \
        bp[1] = make_uint4(f2tf(fb1.x), f2tf(fb1.y), f2tf(fb1.z), f2tf(fb1.w));   \
    }

    FETCH2();
    STORE2(0);
    __syncthreads();
    int buf = 0;
    const int T = 13;
    for (int t = 0; t < T; t++) {
        bool more = (t + 1 < T);
        if (more) FETCH2();
        compute_tile(As[buf], Bs[buf], acc, m_off, n_off, q, c);
        if (more) STORE2(buf ^ 1);
        __syncthreads();
        buf ^= 1;
    }
#undef FETCH2
#undef STORE2

    // epilogue: bias, store h, BN statistics
    float bb0[8], bb1[8];
#pragma unroll
    for (int j = 0; j < 8; j++) {
        int cc = n_off + (j << 3) + (c << 1);
        bb0[j] = g_bsum[(mi << 7) + cc];
        bb1[j] = g_bsum[(mi << 7) + cc + 1];
    }
    float cs0[8], cs1[8], cq0[8], cq1[8];
#pragma unroll
    for (int j = 0; j < 8; j++) { cs0[j] = cs1[j] = cq0[j] = cq1[j] = 0.f; }

#pragma unroll
    for (int i = 0; i < 2; i++) {
        int mA = m0 + m_off + (i << 4) + q;
#pragma unroll
        for (int rh = 0; rh < 2; rh++) {
            int m = mA + (rh << 3);
            if (m < 200) {
                size_t base = (size_t)mi * OFFH2 + ((size_t)m * 768 + bx) * 128;
#pragma unroll
                for (int j = 0; j < 8; j++) {
                    int cc = n_off + (j << 3) + (c << 1);
                    float h0 = acc[i][j][rh * 2] + bb0[j];
                    float h1 = acc[i][j][rh * 2 + 1] + bb1[j];
                    *(float2*)(g_h + base + cc) = make_float2(h0, h1);
                    cs0[j] += h0; cq0[j] += h0 * h0;
                    cs1[j] += h1; cq1[j] += h1 * h1;
                }
            }
        }
    }
    // warp reduce across q (lane bits 2..4)
#pragma unroll
    for (int j = 0; j < 8; j++) {
#pragma unroll
        for (int o = 4; o < 32; o <<= 1) {
            cs0[j] += __shfl_xor_sync(0xffffffffu, cs0[j], o);
            cs1[j] += __shfl_xor_sync(0xffffffffu, cs1[j], o);
            cq0[j] += __shfl_xor_sync(0xffffffffu, cq0[j], o);
            cq1[j] += __shfl_xor_sync(0xffffffffu, cq1[j], o);
        }
        if (q == 0) {
            int cc = n_off + (j << 3) + (c << 1);
            atomicAdd(&sS[cc], cs0[j]);
            atomicAdd(&sS[cc + 1], cs1[j]);
            atomicAdd(&sQ[cc], cq0[j]);
            atomicAdd(&sQ[cc + 1], cq1[j]);
        }
    }
    __syncthreads();
    if (tid < 128) {
        atomicAdd(&g_stats[(mi << 7) + tid], sS[tid]);
        atomicAdd(&g_stats[256 + (mi << 7) + tid], sQ[tid]);
    }
}

// ---------------- GEMM 3: out = relu(relu(BN(h)) @ W_out + b_out) ------------
__global__ __launch_bounds__(256) void k_gemm_out(const float* __restrict__ Wout,
                                                  const float* __restrict__ bout,
                                                  float* __restrict__ out) {
    __shared__ uint32_t As[2][128][20];
    __shared__ uint32_t Bs[2][16][136];
    __shared__ float sSc[256], sBi[256], sBo[128];
    const int tid = threadIdx.x;
    sSc[tid] = g_scale[tid];
    sBi[tid] = g_bias[tid];
    if (tid < 128) sBo[tid] = bout[tid];
    __syncthreads();

    const int lane = tid & 31;
    const int q = lane >> 2, c = lane & 3;
    const int m_off = ((tid >> 5) & 3) << 5;
    const int n_off = (tid >> 7) << 6;
    const int r0 = blockIdx.x << 7;

    const int arow = tid & 127, acol = (tid >> 7) << 3;
    const int brow = tid >> 4, bcol = (tid & 15) << 3;
    const int rA = r0 + arow;

    const float* Bp = Wout + (size_t)brow * 128 + bcol;

    float acc[2][8][4];
#pragma unroll
    for (int i = 0; i < 2; i++)
#pragma unroll
        for (int j = 0; j < 8; j++)
#pragma unroll
            for (int p = 0; p < 4; p++) acc[i][j][p] = 0.f;

    float4 fa0, fa1, fb0, fb1;
    int tk = 0;
#define FETCH3()                                                                \
    {                                                                           \
        int k = tk + acol;                                                      \
        const float* p = g_h + (size_t)(k >> 7) * OFFH2 + (size_t)rA * 128 +    \
                         (k & 127);                                             \
        fa0 = *(const float4*)p; fa1 = *(const float4*)(p + 4);                 \
        fa0.x = fmaxf(fmaf(fa0.x, sSc[k], sBi[k]), 0.f);                        \
        fa0.y = fmaxf(fmaf(fa0.y, sSc[k + 1], sBi[k + 1]), 0.f);                \
        fa0.z = fmaxf(fmaf(fa0.z, sSc[k + 2], sBi[k + 2]), 0.f);                \
        fa0.w = fmaxf(fmaf(fa0.w, sSc[k + 3], sBi[k + 3]), 0.f);                \
        fa1.x = fmaxf(fmaf(fa1.x, sSc[k + 4], sBi[k + 4]), 0.f);                \
        fa1.y = fmaxf(fmaf(fa1.y, sSc[k + 5], sBi[k + 5]), 0.f);                \
        fa1.z = fmaxf(fmaf(fa1.z, sSc[k + 6], sBi[k + 6]), 0.f);                \
        fa1.w = fmaxf(fmaf(fa1.w, sSc[k + 7], sBi[k + 7]), 0.f);                \
        fb0 = *(const float4*)Bp; fb1 = *(const float4*)(Bp + 4);               \
        Bp += 16 * 128; tk += 16;                                               \
    }
#define STORE3(b)                                                                 \
    {                                                                             \
        uint4* ap = (uint4*)&As[b][arow][acol];                                   \
        ap[0] = make_uint4(f2tf(fa0.x), f2tf(fa0.y), f2tf(fa0.z), f2tf(fa0.w));   \
        ap[1] = make_uint4(f2tf(fa1.x), f2tf(fa1.y), f2tf(fa1.z), f2tf(fa1.w));   \
        uint4* bp = (uint4*)&Bs[b][brow][bcol];                                   \
        bp[0] = make_uint4(f2tf(fb0.x), f2tf(fb0.y), f2tf(fb0.z), f2tf(fb0.w));   \
        bp[1] = make_uint4(f2tf(fb1.x), f2tf(fb1.y), f2tf(fb1.z), f2tf(fb1.w));   \
    }

    FETCH3();
    STORE3(0);
    __syncthreads();
    int buf = 0;
    const int T = 16;
    for (int t = 0; t < T; t++) {
        bool more = (t + 1 < T);
        if (more) FETCH3();
        compute_tile(As[buf], Bs[buf], acc, m_off, n_off, q, c);
        if (more) STORE3(buf ^ 1);
        __syncthreads();
        buf ^= 1;
    }
#undef FETCH3
#undef STORE3

#pragma unroll
    for (int i = 0; i < 2; i++) {
        int r1 = r0 + m_off + (i << 4) + q;
#pragma unroll
        for (int rh = 0; rh < 2; rh++) {
            int r = r1 + (rh << 3);
            int n = r / 768;
            int bs_ = r - n * 768;
            int b = bs_ / 96;
            int s = bs_ - b * 96;
            float* dst = out + (((size_t)b * 200 + n) * 96 + s) * 128;
#pragma unroll
            for (int j = 0; j < 8; j++) {
                int cc = n_off + (j << 3) + (c << 1);
                float o0 = fmaxf(acc[i][j][rh * 2] + sBo[cc], 0.f);
                float o1 = fmaxf(acc[i][j][rh * 2 + 1] + sBo[cc + 1], 0.f);
                *(float2*)(dst + cc) = make_float2(o0, o1);
            }
        }
    }
}

// ---------------- launch ----------------
extern "C" void kernel_launch(void* const* d_in, const int* in_sizes, int n_in,
                              void* d_out, int out_size) {
    const float* x        = (const float*)d_in[0];
    const float* attn     = (const float*)d_in[1];
    const float* supports = (const float*)d_in[2];
    const float* Wc       = (const float*)d_in[3];
    const float* bc       = (const float*)d_in[4];
    const float* gamma    = (const float*)d_in[5];
    const float* beta     = (const float*)d_in[6];
    const float* Wout     = (const float*)d_in[7];
    const float* bout     = (const float*)d_in[8];
    float* out = (float*)d_out;

    k_attn_mean<<<157, 256>>>(attn);
    k_prep<<<128, 256>>>(Wc, bc);
    k_procmap<<<dim3(200, 2), 256>>>(supports);
    k_norm_pad<<<416, 256>>>();
    k_zero_xwpad<<<1536, 256>>>();
    k_gemm_xw<<<dim3(2, 1200), 256>>>(x);
    k_gemm_an<<<dim3(768, 2, 2), 256>>>();
    k_bnparams<<<1, 256>>>(gamma, beta);
    k_gemm_out<<<1200, 256>>>(Wout, bout, out);
}

// round 4
// speedup vs baseline: 2.0947x; 1.0002x over previous
#include <cuda_runtime.h>
#include <math.h>
#include <stdint.h>

// ---------------- problem constants ----------------
#define OFFH2 19660800ULL   // 200*768*128 per-map h tensor

// ---------------- scratch (static device globals) ----------------
__device__ float g_W2[128 * 256];          // summed conv weights [k][map*128+g]
__device__ float g_bsum[256];
__device__ float g_map1raw[200 * 200];
__device__ float g_Msym[2 * 200 * 200];
__device__ float g_dinv[2 * 200];
__device__ float g_An[2 * 256 * 208];      // padded normalized adjacency
__device__ float g_xw[2ULL * 208 * 98304]; // [map][n(208)][bs][d]
__device__ float g_h[2ULL * 19660800ULL];  // [map][m*768+bs][d]
__device__ float g_stats[512];
__device__ float g_scale[256];
__device__ float g_bias[256];

// ---------------- tf32 helpers ----------------
__device__ __forceinline__ uint32_t f2tf(float x) {
    uint32_t r;
    asm("cvt.rna.tf32.f32 %0, %1;" : "=r"(r) : "f"(x));
    return r;
}

__device__ __forceinline__ void mma_tf32(float* d, const uint32_t* a, const uint32_t* b) {
    asm volatile(
        "mma.sync.aligned.m16n8k8.row.col.f32.tf32.tf32.f32 "
        "{%0,%1,%2,%3}, {%4,%5,%6,%7}, {%8,%9}, {%0,%1,%2,%3};"
        : "+f"(d[0]), "+f"(d[1]), "+f"(d[2]), "+f"(d[3])
        : "r"(a[0]), "r"(a[1]), "r"(a[2]), "r"(a[3]), "r"(b[0]), "r"(b[1]));
}

// one BK=16 tile of 128x128 per block; warp tile 32x64 (2 mtiles x 8 ntiles)
__device__ __forceinline__ void compute_tile(const uint32_t (*As)[20],
                                             const uint32_t (*Bs)[136],
                                             float acc[2][8][4],
                                             int m_off, int n_off, int q, int c) {
#pragma unroll
    for (int s = 0; s < 2; s++) {
        const int ks = s << 3;
        uint32_t a[2][4];
#pragma unroll
        for (int i = 0; i < 2; i++) {
            const int mr = m_off + (i << 4) + q;
            a[i][0] = As[mr][ks + c];
            a[i][1] = As[mr + 8][ks + c];
            a[i][2] = As[mr][ks + c + 4];
            a[i][3] = As[mr + 8][ks + c + 4];
        }
        uint32_t b[8][2];
#pragma unroll
        for (int j = 0; j < 8; j++) {
            const int nn = n_off + (j << 3) + q;
            b[j][0] = Bs[ks + c][nn];
            b[j][1] = Bs[ks + c + 4][nn];
        }
#pragma unroll
        for (int i = 0; i < 2; i++)
#pragma unroll
            for (int j = 0; j < 8; j++) mma_tf32(acc[i][j], a[i], b[j]);
    }
}

// ---------------- small prep kernels ----------------
__global__ void k_attn_mean(const float* __restrict__ attn) {
    int e = blockIdx.x * 256 + threadIdx.x;
    if (e >= 40000) return;
    float s = 0.f;
#pragma unroll 8
    for (int t = 0; t < 64; t++) s += attn[t * 40000 + e];
    g_map1raw[e] = s * (1.f / 64.f);
}

__global__ void k_prep(const float* __restrict__ Wc, const float* __restrict__ bc) {
    int id = blockIdx.x * 256 + threadIdx.x;
    if (id < 32768) {
        int d = id >> 8;
        int cc = id & 255;
        int i = cc >> 7;
        int g = cc & 127;
        g_W2[id] = Wc[((i * 2 + 0) * 128 + d) * 128 + g] +
                   Wc[((i * 2 + 1) * 128 + d) * 128 + g];
    }
    if (id < 512) g_stats[id] = 0.f;
    if (id < 256) {
        int i = id >> 7, g = id & 127;
        g_bsum[id] = bc[(i * 2 + 0) * 128 + g] + bc[(i * 2 + 1) * 128 + g];
    }
}

__global__ void k_procmap(const float* __restrict__ supports) {
    int m = blockIdx.x;
    int mi = blockIdx.y;
    int t = threadIdx.x;
    const float* src = (mi == 0) ? supports : g_map1raw;
    float v = 0.f;
    if (t < 200) {
        float a = (m >= t) ? src[m * 200 + t] : src[t * 200 + m];
        float aa = fabsf(a);
        v = (aa > 0.01f) ? aa : 0.f;
        g_Msym[mi * 40000 + m * 200 + t] = v;
    }
    __shared__ float red[8];
    float s = v;
#pragma unroll
    for (int o = 16; o; o >>= 1) s += __shfl_xor_sync(0xffffffffu, s, o);
    if ((t & 31) == 0) red[t >> 5] = s;
    __syncthreads();
    if (t == 0) {
        float tot = 1.0f;
#pragma unroll
        for (int w = 0; w < 8; w++) tot += red[w];
        g_dinv[mi * 200 + m] = (tot > 0.f) ? rsqrtf(tot) : 0.f;
    }
}

// An padded to [2][256][208], zeros outside [200,200)
__global__ void k_norm_pad() {
    int id = blockIdx.x * 256 + threadIdx.x;
    if (id >= 2 * 256 * 208) return;
    int mi = id / (256 * 208);
    int rem = id - mi * 256 * 208;
    int m = rem / 208;
    int k = rem - m * 208;
    float val = 0.f;
    if (m < 200 && k < 200) {
        float a = g_Msym[mi * 40000 + m * 200 + k] + ((m == k) ? 1.f : 0.f);
        val = g_dinv[mi * 200 + m] * a * g_dinv[mi * 200 + k];
    }
    g_An[id] = val;
}

// zero g_xw pad rows n in [200,208)
__global__ void k_zero_xwpad() {
    int idx = blockIdx.x * 256 + threadIdx.x;   // float4 index, total 393216
    int mi = idx / 196608;
    int r = idx - mi * 196608;
    int n = 200 + r / 24576;
    int cc = (r - (n - 200) * 24576) * 4;
    float4 z = make_float4(0.f, 0.f, 0.f, 0.f);
    *(float4*)(g_xw + ((size_t)(mi * 208 + n)) * 98304 + cc) = z;
}

__global__ void k_bnparams(const float* __restrict__ gamma, const float* __restrict__ beta) {
    int c = threadIdx.x;
    const float inv = 1.f / 153600.f;
    float mu = g_stats[c] * inv;
    float var = g_stats[256 + c] * inv - mu * mu;
    float sc = gamma[c] * rsqrtf(var + 1e-5f);
    g_scale[c] = sc;
    g_bias[c] = beta[c] - mu * sc;
}

// ---------------- GEMM 1: xw = X @ W2  (153600x128 @ 128x256) ----------------
__global__ __launch_bounds__(256) void k_gemm_xw(const float* __restrict__ X) {
    __shared__ uint32_t As[2][128][20];
    __shared__ uint32_t Bs[2][16][136];
    const int tid = threadIdx.x;
    const int lane = tid & 31;
    const int q = lane >> 2, c = lane & 3;
    const int m_off = ((tid >> 5) & 3) << 5;
    const int n_off = (tid >> 7) << 6;
    const int mi = blockIdx.x;
    const int r0 = blockIdx.y << 7;

    const int arow = tid & 127, acol = (tid >> 7) << 3;
    const int brow = tid >> 4, bcol = (tid & 15) << 3;

    const float* Ap = X + (size_t)(r0 + arow) * 128 + acol;
    const float* Bp = g_W2 + (size_t)brow * 256 + (mi << 7) + bcol;

    float acc[2][8][4];
#pragma unroll
    for (int i = 0; i < 2; i++)
#pragma unroll
        for (int j = 0; j < 8; j++)
#pragma unroll
            for (int p = 0; p < 4; p++) acc[i][j][p] = 0.f;

    float4 fa0, fa1, fb0, fb1;
#define FETCH1()                                              \
    {                                                         \
        fa0 = *(const float4*)Ap; fa1 = *(const float4*)(Ap + 4); \
        fb0 = *(const float4*)Bp; fb1 = *(const float4*)(Bp + 4); \
        Ap += 16; Bp += 16 * 256;                             \
    }
#define STORE1(b)                                                                 \
    {                                                                             \
        uint4* ap = (uint4*)&As[b][arow][acol];                                   \
        ap[0] = make_uint4(f2tf(fa0.x), f2tf(fa0.y), f2tf(fa0.z), f2tf(fa0.w));   \
        ap[1] = make_uint4(f2tf(fa1.x), f2tf(fa1.y), f2tf(fa1.z), f2tf(fa1.w));   \
        uint4* bp = (uint4*)&Bs[b][brow][bcol];                                   \
        bp[0] = make_uint4(f2tf(fb0.x), f2tf(fb0.y), f2tf(fb0.z), f2tf(fb0.w));   \
        bp[1] = make_uint4(f2tf(fb1.x), f2tf(fb1.y), f2tf(fb1.z), f2tf(fb1.w));   \
    }

    FETCH1();
    STORE1(0);
    __syncthreads();
    int buf = 0;
    const int T = 8;
    for (int t = 0; t < T; t++) {
        bool more = (t + 1 < T);
        if (more) FETCH1();
        compute_tile(As[buf], Bs[buf], acc, m_off, n_off, q, c);
        if (more) STORE1(buf ^ 1);
        __syncthreads();
        buf ^= 1;
    }
#undef FETCH1
#undef STORE1

#pragma unroll
    for (int i = 0; i < 2; i++) {
        int r1 = r0 + m_off + (i << 4) + q;
#pragma unroll
        for (int rh = 0; rh < 2; rh++) {
            int r = r1 + (rh << 3);
            int b = r / 19200;
            int rem = r - b * 19200;
            int n = rem / 96;
            int s = rem - n * 96;
            size_t base = ((size_t)(mi * 208 + n) * 768 + (b * 96 + s)) * 128;
#pragma unroll
            for (int j = 0; j < 8; j++) {
                int cc = n_off + (j << 3) + (c << 1);
                *(float2*)(g_xw + base + cc) =
                    make_float2(acc[i][j][rh * 2], acc[i][j][rh * 2 + 1]);
            }
        }
    }
}

// ---------------- GEMM 2: h = An @ xw  (256x208 @ 208x98304, per map) --------
__global__ __launch_bounds__(256) void k_gemm_an() {
    __shared__ uint32_t As[2][128][20];
    __shared__ uint32_t Bs[2][16][136];
    __shared__ float sS[128], sQ[128];
    const int tid = threadIdx.x;
    const int lane = tid & 31;
    const int q = lane >> 2, c = lane & 3;
    const int m_off = ((tid >> 5) & 3) << 5;
    const int n_off = (tid >> 7) << 6;
    const int bx = blockIdx.x;        // bs
    const int m0 = blockIdx.y << 7;   // 0 / 128
    const int mi = blockIdx.z;

    if (tid < 128) { sS[tid] = 0.f; sQ[tid] = 0.f; }

    const int arow = tid & 127, acol = (tid >> 7) << 3;
    const int brow = tid >> 4, bcol = (tid & 15) << 3;

    const float* Ap = g_An + (size_t)mi * (256 * 208) + (size_t)(m0 + arow) * 208 + acol;
    const float* Bp = g_xw + (size_t)mi * (208ULL * 98304) + (size_t)brow * 98304 +
                      (size_t)bx * 128 + bcol;

    float acc[2][8][4];
#pragma unroll
    for (int i = 0; i < 2; i++)
#pragma unroll
        for (int j = 0; j < 8; j++)
#pragma unroll
            for (int p = 0; p < 4; p++) acc[i][j][p] = 0.f;

    float4 fa0, fa1, fb0, fb1;
#define FETCH2()                                              \
    {                                                         \
        fa0 = *(const float4*)Ap; fa1 = *(const float4*)(Ap + 4); \
        fb0 = *(const float4*)Bp; fb1 = *(const float4*)(Bp + 4); \
        Ap += 16; Bp += (size_t)16 * 98304;                   \
    }
#define STORE2(b)                                                                 \
    {                                                                             \
        uint4* ap = (uint4*)&As[b][arow][acol];                                   \
        ap[0] = make_uint4(f2tf(fa0.x), f2tf(fa0.y), f2tf(fa0.z), f2tf(fa0.w));   \
        ap[1] = make_uint4(f2tf(fa1.x), f2tf(fa1.y), f2tf(fa1.z), f2tf(fa1.w));   \
        uint4* bp = (uint4*)&Bs[b][brow][bcol];                                   \
        bp[0] = make_uint4(f2tf(fb0.x), f2tf(fb0.y), f2tf(fb0.z), f2tf(fb0.w));   \
        bp[1] = make_uint4(f2tf(fb1.x), f2tf(fb1.y), f2tf(fb1.z), f2tf(fb1.w));   \
    }

    FETCH2();
    STORE2(0);
    __syncthreads();
    int buf = 0;
    const int T = 13;
    for (int t = 0; t < T; t++) {
        bool more = (t + 1 < T);
        if (more) FETCH2();
        compute_tile(As[buf], Bs[buf], acc, m_off, n_off, q, c);
        if (more) STORE2(buf ^ 1);
        __syncthreads();
        buf ^= 1;
    }
#undef FETCH2
#undef STORE2

    // epilogue: bias, store h, BN statistics
    float bb0[8], bb1[8];
#pragma unroll
    for (int j = 0; j < 8; j++) {
        int cc = n_off + (j << 3) + (c << 1);
        bb0[j] = g_bsum[(mi << 7) + cc];
        bb1[j] = g_bsum[(mi << 7) + cc + 1];
    }
    float cs0[8], cs1[8], cq0[8], cq1[8];
#pragma unroll
    for (int j = 0; j < 8; j++) { cs0[j] = cs1[j] = cq0[j] = cq1[j] = 0.f; }

#pragma unroll
    for (int i = 0; i < 2; i++) {
        int mA = m0 + m_off + (i << 4) + q;
#pragma unroll
        for (int rh = 0; rh < 2; rh++) {
            int m = mA + (rh << 3);
            if (m < 200) {
                size_t base = (size_t)mi * OFFH2 + ((size_t)m * 768 + bx) * 128;
#pragma unroll
                for (int j = 0; j < 8; j++) {
                    int cc = n_off + (j << 3) + (c << 1);
                    float h0 = acc[i][j][rh * 2] + bb0[j];
                    float h1 = acc[i][j][rh * 2 + 1] + bb1[j];
                    *(float2*)(g_h + base + cc) = make_float2(h0, h1);
                    cs0[j] += h0; cq0[j] += h0 * h0;
                    cs1[j] += h1; cq1[j] += h1 * h1;
                }
            }
        }
    }
    // warp reduce across q (lane bits 2..4)
#pragma unroll
    for (int j = 0; j < 8; j++) {
#pragma unroll
        for (int o = 4; o < 32; o <<= 1) {
            cs0[j] += __shfl_xor_sync(0xffffffffu, cs0[j], o);
            cs1[j] += __shfl_xor_sync(0xffffffffu, cs1[j], o);
            cq0[j] += __shfl_xor_sync(0xffffffffu, cq0[j], o);
            cq1[j] += __shfl_xor_sync(0xffffffffu, cq1[j], o);
        }
        if (q == 0) {
            int cc = n_off + (j << 3) + (c << 1);
            atomicAdd(&sS[cc], cs0[j]);
            atomicAdd(&sS[cc + 1], cs1[j]);
            atomicAdd(&sQ[cc], cq0[j]);
            atomicAdd(&sQ[cc + 1], cq1[j]);
        }
    }
    __syncthreads();
    if (tid < 128) {
        atomicAdd(&g_stats[(mi << 7) + tid], sS[tid]);
        atomicAdd(&g_stats[256 + (mi << 7) + tid], sQ[tid]);
    }
}

// ---------------- GEMM 3: out = relu(relu(BN(h)) @ W_out + b_out) ------------
__global__ __launch_bounds__(256) void k_gemm_out(const float* __restrict__ Wout,
                                                  const float* __restrict__ bout,
                                                  float* __restrict__ out) {
    __shared__ uint32_t As[2][128][20];
    __shared__ uint32_t Bs[2][16][136];
    __shared__ float sSc[256], sBi[256], sBo[128];
    const int tid = threadIdx.x;
    sSc[tid] = g_scale[tid];
    sBi[tid] = g_bias[tid];
    if (tid < 128) sBo[tid] = bout[tid];
    __syncthreads();

    const int lane = tid & 31;
    const int q = lane >> 2, c = lane & 3;
    const int m_off = ((tid >> 5) & 3) << 5;
    const int n_off = (tid >> 7) << 6;
    const int r0 = blockIdx.x << 7;

    const int arow = tid & 127, acol = (tid >> 7) << 3;
    const int brow = tid >> 4, bcol = (tid & 15) << 3;
    const int rA = r0 + arow;

    const float* Bp = Wout + (size_t)brow * 128 + bcol;

    float acc[2][8][4];
#pragma unroll
    for (int i = 0; i < 2; i++)
#pragma unroll
        for (int j = 0; j < 8; j++)
#pragma unroll
            for (int p = 0; p < 4; p++) acc[i][j][p] = 0.f;

    float4 fa0, fa1, fb0, fb1;
    int tk = 0;
#define FETCH3()                                                                \
    {                                                                           \
        int k = tk + acol;                                                      \
        const float* p = g_h + (size_t)(k >> 7) * OFFH2 + (size_t)rA * 128 +    \
                         (k & 127);                                             \
        fa0 = *(const float4*)p; fa1 = *(const float4*)(p + 4);                 \
        fa0.x = fmaxf(fmaf(fa0.x, sSc[k], sBi[k]), 0.f);                        \
        fa0.y = fmaxf(fmaf(fa0.y, sSc[k + 1], sBi[k + 1]), 0.f);                \
        fa0.z = fmaxf(fmaf(fa0.z, sSc[k + 2], sBi[k + 2]), 0.f);                \
        fa0.w = fmaxf(fmaf(fa0.w, sSc[k + 3], sBi[k + 3]), 0.f);                \
        fa1.x = fmaxf(fmaf(fa1.x, sSc[k + 4], sBi[k + 4]), 0.f);                \
        fa1.y = fmaxf(fmaf(fa1.y, sSc[k + 5], sBi[k + 5]), 0.f);                \
        fa1.z = fmaxf(fmaf(fa1.z, sSc[k + 6], sBi[k + 6]), 0.f);                \
        fa1.w = fmaxf(fmaf(fa1.w, sSc[k + 7], sBi[k + 7]), 0.f);                \
        fb0 = *(const float4*)Bp; fb1 = *(const float4*)(Bp + 4);               \
        Bp += 16 * 128; tk += 16;                                               \
    }
#define STORE3(b)                                                                 \
    {                                                                             \
        uint4* ap = (uint4*)&As[b][arow][acol];                                   \
        ap[0] = make_uint4(f2tf(fa0.x), f2tf(fa0.y), f2tf(fa0.z), f2tf(fa0.w));   \
        ap[1] = make_uint4(f2tf(fa1.x), f2tf(fa1.y), f2tf(fa1.z), f2tf(fa1.w));   \
        uint4* bp = (uint4*)&Bs[b][brow][bcol];                                   \
        bp[0] = make_uint4(f2tf(fb0.x), f2tf(fb0.y), f2tf(fb0.z), f2tf(fb0.w));   \
        bp[1] = make_uint4(f2tf(fb1.x), f2tf(fb1.y), f2tf(fb1.z), f2tf(fb1.w));   \
    }

    FETCH3();
    STORE3(0);
    __syncthreads();
    int buf = 0;
    const int T = 16;
    for (int t = 0; t < T; t++) {
        bool more = (t + 1 < T);
        if (more) FETCH3();
        compute_tile(As[buf], Bs[buf], acc, m_off, n_off, q, c);
        if (more) STORE3(buf ^ 1);
        __syncthreads();
        buf ^= 1;
    }
#undef FETCH3
#undef STORE3

#pragma unroll
    for (int i = 0; i < 2; i++) {
        int r1 = r0 + m_off + (i << 4) + q;
#pragma unroll
        for (int rh = 0; rh < 2; rh++) {
            int r = r1 + (rh << 3);
            int n = r / 768;
            int bs_ = r - n * 768;
            int b = bs_ / 96;
            int s = bs_ - b * 96;
            float* dst = out + (((size_t)b * 200 + n) * 96 + s) * 128;
#pragma unroll
            for (int j = 0; j < 8; j++) {
                int cc = n_off + (j << 3) + (c << 1);
                float o0 = fmaxf(acc[i][j][rh * 2] + sBo[cc], 0.f);
                float o1 = fmaxf(acc[i][j][rh * 2 + 1] + sBo[cc + 1], 0.f);
                *(float2*)(dst + cc) = make_float2(o0, o1);
            }
        }
    }
}

// ---------------- launch ----------------
extern "C" void kernel_launch(void* const* d_in, const int* in_sizes, int n_in,
                              void* d_out, int out_size) {
    const float* x        = (const float*)d_in[0];
    const float* attn     = (const float*)d_in[1];
    const float* supports = (const float*)d_in[2];
    const float* Wc       = (const float*)d_in[3];
    const float* bc       = (const float*)d_in[4];
    const float* gamma    = (const float*)d_in[5];
    const float* beta     = (const float*)d_in[6];
    const float* Wout     = (const float*)d_in[7];
    const float* bout     = (const float*)d_in[8];
    float* out = (float*)d_out;

    k_attn_mean<<<157, 256>>>(attn);
    k_prep<<<128, 256>>>(Wc, bc);
    k_procmap<<<dim3(200, 2), 256>>>(supports);
    k_norm_pad<<<416, 256>>>();
    k_zero_xwpad<<<1536, 256>>>();
    k_gemm_xw<<<dim3(2, 1200), 256>>>(x);
    k_gemm_an<<<dim3(768, 2, 2), 256>>>();
    k_bnparams<<<1, 256>>>(gamma, beta);
    k_gemm_out<<<1200, 256>>>(Wout, bout, out);
}